// round 10
// baseline (speedup 1.0000x reference)
#include <cuda_runtime.h>
#include <cuda_bf16.h>

// PyramidROIAlign: 2 blocks per ROI, 224 threads (R9 structure), with the
// bilinear lerp reformulated as a 4-weight dot product evaluated in packed
// f32x2 (mul.rn.f32x2 / fma.rn.f32x2): 8 math instructions per float4 task
// instead of 24. Weights pre-packed per pool position in smem.

#define TPB    224
#define NPOS   49
#define C      256
#define NTASK  (NPOS * (C / 4))   // 3136 float4 tasks per ROI
#define HTASK  (NTASK / 2)        // 1568 per block

typedef unsigned long long u64;

__device__ __forceinline__ u64 mulx2(u64 a, u64 b) {
    u64 d; asm("mul.rn.f32x2 %0, %1, %2;" : "=l"(d) : "l"(a), "l"(b)); return d;
}
__device__ __forceinline__ u64 fmax2(u64 a, u64 b, u64 c) {
    u64 d; asm("fma.rn.f32x2 %0, %1, %2, %3;" : "=l"(d) : "l"(a), "l"(b), "l"(c)); return d;
}

struct __align__(16) PPD {
    const float *p00, *p01, *p10, *p11;   // corner base pointers (channel 0)
    float4 wlo;                           // (w00,w00, w01,w01) packed pairs
    float4 whi;                           // (w10,w10, w11,w11) packed pairs
};

__device__ __forceinline__ float4 bilerp_x2(float4 v00, float4 v01, float4 v10, float4 v11,
                                            const float4& wlo, const float4& whi) {
    const u64* wl = (const u64*)&wlo;     // wl[0]=w00 pair, wl[1]=w01 pair
    const u64* wh = (const u64*)&whi;     // wh[0]=w10 pair, wh[1]=w11 pair
    const u64* a = (const u64*)&v00;
    const u64* b = (const u64*)&v01;
    const u64* c = (const u64*)&v10;
    const u64* d = (const u64*)&v11;

    u64 rlo = mulx2(a[0], wl[0]);
    rlo = fmax2(b[0], wl[1], rlo);
    rlo = fmax2(c[0], wh[0], rlo);
    rlo = fmax2(d[0], wh[1], rlo);

    u64 rhi = mulx2(a[1], wl[0]);
    rhi = fmax2(b[1], wl[1], rhi);
    rhi = fmax2(c[1], wh[0], rhi);
    rhi = fmax2(d[1], wh[1], rhi);

    float4 r;
    ((u64*)&r)[0] = rlo;
    ((u64*)&r)[1] = rhi;
    return r;
}

__global__ __launch_bounds__(TPB) void pyramid_roi_align_kernel(
    const float* __restrict__ boxes,   // [N,4] y1,x1,y2,x2 normalized
    const float* __restrict__ meta,    // [93], meta[4],meta[5] = image H,W
    const float* __restrict__ P2,      // [256,256,256]
    const float* __restrict__ P3,      // [128,128,256]
    const float* __restrict__ P4,      // [64,64,256]
    const float* __restrict__ P5,      // [32,32,256]
    float* __restrict__ out)           // [N,49,256]
{
    const int roi  = blockIdx.x >> 1;
    const int half = blockIdx.x & 1;
    const int tid  = threadIdx.x;

    __shared__ PPD s_pp[NPOS];

    if (tid < NPOS) {
        const float y1 = boxes[roi * 4 + 0];
        const float x1 = boxes[roi * 4 + 1];
        const float y2 = boxes[roi * 4 + 2];
        const float x2 = boxes[roi * 4 + 3];
        const float h = y2 - y1;
        const float w = x2 - x1;

        // roi_level = clip(4 + round(log2(sqrt(h*w) / (224/sqrt(imgH*imgW)))), 2, 5)
        const float img_h = meta[4];
        const float img_w = meta[5];
        const float scale = 224.0f / sqrtf(img_h * img_w);
        const float lvl_f = log2f(sqrtf(h * w) / scale);
        int level = 4 + (int)rintf(lvl_f);        // round-half-even == jnp.round
        level = min(max(level, 2), 5);

        const int H = 1024 >> level;              // 256,128,64,32
        const int W = H;
        const float* base = (level == 2) ? P2 : (level == 3) ? P3
                          : (level == 4) ? P4 : P5;

        const int py = tid / 7;
        const int px = tid - py * 7;
        const float ys = (y1 + (float)py * (1.0f / 6.0f) * h) * (float)(H - 1);
        const float xs = (x1 + (float)px * (1.0f / 6.0f) * w) * (float)(W - 1);

        const float y0f = fminf(fmaxf(floorf(ys), 0.0f), (float)(H - 1));
        const float x0f = fminf(fmaxf(floorf(xs), 0.0f), (float)(W - 1));
        const int y0  = (int)y0f;
        const int x0  = (int)x0f;
        const int y1i = min(y0 + 1, H - 1);
        const int x1i = min(x0 + 1, W - 1);

        const float wx = xs - x0f;
        const float wy = ys - y0f;
        const float w00 = (1.0f - wx) * (1.0f - wy);
        const float w01 = wx * (1.0f - wy);
        const float w10 = (1.0f - wx) * wy;
        const float w11 = wx * wy;

        PPD m;
        m.p00 = base + (y0  * W + x0 ) * C;
        m.p01 = base + (y0  * W + x1i) * C;
        m.p10 = base + (y1i * W + x0 ) * C;
        m.p11 = base + (y1i * W + x1i) * C;
        m.wlo = make_float4(w00, w00, w01, w01);
        m.whi = make_float4(w10, w10, w11, w11);
        s_pp[tid] = m;
    }
    __syncthreads();

    float* __restrict__ out_base = out + (long long)roi * (NTASK * 4);
    const int t0 = half * HTASK;       // this block's first task within the ROI

    // 1568 tasks = 3 double-iterations (1344) + 1 single (224).
    #pragma unroll 1
    for (int k = 0; k < 3; k++) {
        const int iA = t0 + tid + k * (2 * TPB);
        const int iB = iA + TPB;

        const int posA = iA >> 6;
        const int cgA  = (iA & 63) << 2;
        const PPD& mA  = s_pp[posA];
        const float* pA00 = mA.p00 + cgA;
        const float* pA01 = mA.p01 + cgA;
        const float* pA10 = mA.p10 + cgA;
        const float* pA11 = mA.p11 + cgA;

        const int posB = iB >> 6;
        const int cgB  = (iB & 63) << 2;
        const PPD& mB  = s_pp[posB];
        const float* pB00 = mB.p00 + cgB;
        const float* pB01 = mB.p01 + cgB;
        const float* pB10 = mB.p10 + cgB;
        const float* pB11 = mB.p11 + cgB;

        // ---- 8 independent LDG.128
        const float4 a00 = __ldg((const float4*)pA00);
        const float4 a01 = __ldg((const float4*)pA01);
        const float4 a10 = __ldg((const float4*)pA10);
        const float4 a11 = __ldg((const float4*)pA11);
        const float4 b00 = __ldg((const float4*)pB00);
        const float4 b01 = __ldg((const float4*)pB01);
        const float4 b10 = __ldg((const float4*)pB10);
        const float4 b11 = __ldg((const float4*)pB11);

        const float4 rA = bilerp_x2(a00, a01, a10, a11, mA.wlo, mA.whi);
        __stcs((float4*)(out_base + iA * 4), rA);

        const float4 rB = bilerp_x2(b00, b01, b10, b11, mB.wlo, mB.whi);
        __stcs((float4*)(out_base + iB * 4), rB);
    }

    // final single iteration
    {
        const int i   = t0 + tid + 6 * TPB;
        const int pos = i >> 6;
        const int cg  = (i & 63) << 2;
        const PPD& m  = s_pp[pos];
        const float4 v00 = __ldg((const float4*)(m.p00 + cg));
        const float4 v01 = __ldg((const float4*)(m.p01 + cg));
        const float4 v10 = __ldg((const float4*)(m.p10 + cg));
        const float4 v11 = __ldg((const float4*)(m.p11 + cg));

        const float4 r = bilerp_x2(v00, v01, v10, v11, m.wlo, m.whi);
        __stcs((float4*)(out_base + i * 4), r);
    }
}

extern "C" void kernel_launch(void* const* d_in, const int* in_sizes, int n_in,
                              void* d_out, int out_size) {
    const float* boxes = (const float*)d_in[0];   // ROIboxes [1,N,4]
    const float* meta  = (const float*)d_in[1];   // image_meta [1,93]
    const float* P2    = (const float*)d_in[2];
    const float* P3    = (const float*)d_in[3];
    const float* P4    = (const float*)d_in[4];
    const float* P5    = (const float*)d_in[5];
    float* out = (float*)d_out;

    const int N = in_sizes[0] / 4;
    pyramid_roi_align_kernel<<<N * 2, TPB>>>(boxes, meta, P2, P3, P4, P5, out);
}

// round 13
// speedup vs baseline: 1.1536x; 1.1536x over previous
#include <cuda_runtime.h>
#include <cuda_bf16.h>

// PyramidROIAlign: 7 blocks per ROI x 64 threads (grid 7N).
// Each block owns 7 pool positions (448 float4 tasks = 7 per thread).
// Iteration k uses position k exactly -> warp-uniform s_pp[k] metadata,
// zero per-task index math. Minimal registers (<=32) so 32 blocks/SM =
// 2048 threads = 100% occupancy ceiling; 7000 blocks give a smooth tail.

#define TPB          64
#define SEGS         7          // blocks per ROI
#define POS_PER_BLK  7
#define NPOS         49
#define C            256
#define ROI_FLOATS   (NPOS * C)        // 12544
#define SEG_FLOATS   (POS_PER_BLK * C) // 1792

struct __align__(16) PPD {
    const float *p00, *p01, *p10, *p11;  // corner row pointers (channel 0)
    float wx, wy, pad0, pad1;
};

__global__ __launch_bounds__(TPB) void pyramid_roi_align_kernel(
    const float* __restrict__ boxes,   // [N,4] y1,x1,y2,x2 normalized
    const float* __restrict__ meta,    // [93], meta[4],meta[5] = image H,W
    const float* __restrict__ P2,      // [256,256,256]
    const float* __restrict__ P3,      // [128,128,256]
    const float* __restrict__ P4,      // [64,64,256]
    const float* __restrict__ P5,      // [32,32,256]
    float* __restrict__ out)           // [N,49,256]
{
    const int bid = blockIdx.x;
    const int roi = bid / SEGS;
    const int seg = bid - roi * SEGS;
    const int tid = threadIdx.x;

    __shared__ PPD s_pp[POS_PER_BLK];

    if (tid < POS_PER_BLK) {
        const int pos = seg * POS_PER_BLK + tid;    // global pool position 0..48

        const float y1 = boxes[roi * 4 + 0];
        const float x1 = boxes[roi * 4 + 1];
        const float y2 = boxes[roi * 4 + 2];
        const float x2 = boxes[roi * 4 + 3];
        const float h = y2 - y1;
        const float w = x2 - x1;

        // roi_level = clip(4 + round(log2(sqrt(h*w) / (224/sqrt(imgH*imgW)))), 2, 5)
        const float img_h = meta[4];
        const float img_w = meta[5];
        const float scale = 224.0f / sqrtf(img_h * img_w);
        const float lvl_f = log2f(sqrtf(h * w) / scale);
        int level = 4 + (int)rintf(lvl_f);          // round-half-even == jnp.round
        level = min(max(level, 2), 5);

        const int H = 1024 >> level;                // 256,128,64,32
        const int W = H;
        const float* base = (level == 2) ? P2 : (level == 3) ? P3
                          : (level == 4) ? P4 : P5;

        const int py = pos / 7;
        const int px = pos - py * 7;
        const float ys = (y1 + (float)py * (1.0f / 6.0f) * h) * (float)(H - 1);
        const float xs = (x1 + (float)px * (1.0f / 6.0f) * w) * (float)(W - 1);

        const float y0f = fminf(fmaxf(floorf(ys), 0.0f), (float)(H - 1));
        const float x0f = fminf(fmaxf(floorf(xs), 0.0f), (float)(W - 1));
        const int y0  = (int)y0f;
        const int x0  = (int)x0f;
        const int y1i = min(y0 + 1, H - 1);
        const int x1i = min(x0 + 1, W - 1);

        PPD m;
        m.p00 = base + (y0  * W + x0 ) * C;
        m.p01 = base + (y0  * W + x1i) * C;
        m.p10 = base + (y1i * W + x0 ) * C;
        m.p11 = base + (y1i * W + x1i) * C;
        m.wx  = xs - x0f;
        m.wy  = ys - y0f;
        m.pad0 = 0.0f;
        m.pad1 = 0.0f;
        s_pp[tid] = m;
    }
    __syncthreads();

    // This block's output span: 1792 contiguous floats.
    float* __restrict__ out_seg = out + (long long)roi * ROI_FLOATS + seg * SEG_FLOATS;
    const int cg = tid << 2;                        // channel offset in floats (0..252)

    #pragma unroll 1
    for (int k = 0; k < POS_PER_BLK; k++) {
        const PPD m = s_pp[k];                      // warp-uniform LDS

        const float4 v00 = __ldg((const float4*)(m.p00 + cg));
        const float4 v01 = __ldg((const float4*)(m.p01 + cg));
        const float4 v10 = __ldg((const float4*)(m.p10 + cg));
        const float4 v11 = __ldg((const float4*)(m.p11 + cg));

        const float wx = m.wx, wy = m.wy;
        float4 r;
        float t, b;
        t = v00.x + (v01.x - v00.x) * wx;  b = v10.x + (v11.x - v10.x) * wx;  r.x = t + (b - t) * wy;
        t = v00.y + (v01.y - v00.y) * wx;  b = v10.y + (v11.y - v10.y) * wx;  r.y = t + (b - t) * wy;
        t = v00.z + (v01.z - v00.z) * wx;  b = v10.z + (v11.z - v10.z) * wx;  r.z = t + (b - t) * wy;
        t = v00.w + (v01.w - v00.w) * wx;  b = v10.w + (v11.w - v10.w) * wx;  r.w = t + (b - t) * wy;

        __stcs((float4*)(out_seg + k * C + cg), r);
    }
}

extern "C" void kernel_launch(void* const* d_in, const int* in_sizes, int n_in,
                              void* d_out, int out_size) {
    const float* boxes = (const float*)d_in[0];   // ROIboxes [1,N,4]
    const float* meta  = (const float*)d_in[1];   // image_meta [1,93]
    const float* P2    = (const float*)d_in[2];
    const float* P3    = (const float*)d_in[3];
    const float* P4    = (const float*)d_in[4];
    const float* P5    = (const float*)d_in[5];
    float* out = (float*)d_out;

    const int N = in_sizes[0] / 4;
    pyramid_roi_align_kernel<<<N * SEGS, TPB>>>(boxes, meta, P2, P3, P4, P5, out);
}